// round 1
// baseline (speedup 1.0000x reference)
#include <cuda_runtime.h>
#include <cuda_bf16.h>
#include <math.h>

// Problem constants
#define Bn   16
#define Hh   56
#define Ww   56
#define HW   (Hh*Ww)          // 3136
#define NROW (Bn*HW)          // 50176
#define CIN  384
#define NF   384
#define KK   3
#define D1   (NF*KK)          // 1152

// Scratch (static device globals; allocation in kernel_launch is forbidden)
__device__ float g_y[(size_t)NROW * D1];     // 231 MB: y = x@W1+b1
__device__ float g_out[(size_t)NROW * NF];   // 77 MB: combined pre-GEMM2
__device__ float g_a[Bn * NF];               // channel sums
__device__ float g_abar[Bn * D1];            // softmax weights (b,k,c)

// ---------------------------------------------------------------------------
// Classic SGEMM: C(MxN) = A(MxK) @ B(KxN) + bias(N). 128x128 tile, 8x8/thread.
// M % 128 == 0, N % 128 == 0, K % 16 == 0 (holds for all our shapes).
// ---------------------------------------------------------------------------
__global__ __launch_bounds__(256)
void sgemm_bias(const float* __restrict__ A, const float* __restrict__ B,
                const float* __restrict__ bias, float* __restrict__ C,
                int M, int N, int Kd) {
    const int BM = 128, BN = 128, BK = 16, TM = 8, TN = 8;
    __shared__ float As[BK][BM];
    __shared__ float Bs[BK][BN];

    const int tid = threadIdx.x;
    const int bn0 = blockIdx.x * BN;
    const int bm0 = blockIdx.y * BM;

    const int threadCol = tid % (BN / TN);   // 0..15
    const int threadRow = tid / (BN / TN);   // 0..15

    const int aRow = tid / (BK / 4);         // 0..63
    const int aCol = (tid % (BK / 4)) * 4;   // 0,4,8,12
    const int bRow = tid / (BN / 4);         // 0..7
    const int bCol = (tid % (BN / 4)) * 4;   // 0..124

    float acc[TM][TN] = {};

    const float* Ab = A + (size_t)bm0 * Kd;
    const float* Bb = B + bn0;

    for (int k0 = 0; k0 < Kd; k0 += BK) {
        // Load A tile (128x16), store transposed into As[k][m]
        #pragma unroll
        for (int r = 0; r < BM; r += 64) {
            float4 v = *reinterpret_cast<const float4*>(
                &Ab[(size_t)(aRow + r) * Kd + k0 + aCol]);
            As[aCol + 0][aRow + r] = v.x;
            As[aCol + 1][aRow + r] = v.y;
            As[aCol + 2][aRow + r] = v.z;
            As[aCol + 3][aRow + r] = v.w;
        }
        // Load B tile (16x128)
        #pragma unroll
        for (int r = 0; r < BK; r += 8) {
            float4 v = *reinterpret_cast<const float4*>(
                &Bb[(size_t)(k0 + bRow + r) * N + bCol]);
            *reinterpret_cast<float4*>(&Bs[bRow + r][bCol]) = v;
        }
        __syncthreads();

        #pragma unroll
        for (int k = 0; k < BK; k++) {
            float4 m0 = *reinterpret_cast<const float4*>(&As[k][threadRow * TM]);
            float4 m1 = *reinterpret_cast<const float4*>(&As[k][threadRow * TM + 4]);
            float4 n0 = *reinterpret_cast<const float4*>(&Bs[k][threadCol * TN]);
            float4 n1 = *reinterpret_cast<const float4*>(&Bs[k][threadCol * TN + 4]);
            float regM[8] = {m0.x, m0.y, m0.z, m0.w, m1.x, m1.y, m1.z, m1.w};
            float regN[8] = {n0.x, n0.y, n0.z, n0.w, n1.x, n1.y, n1.z, n1.w};
            #pragma unroll
            for (int i = 0; i < TM; i++)
                #pragma unroll
                for (int j = 0; j < TN; j++)
                    acc[i][j] += regM[i] * regN[j];
        }
        __syncthreads();
    }

    // Epilogue: bias + store
    #pragma unroll
    for (int i = 0; i < TM; i++) {
        int row = bm0 + threadRow * TM + i;
        #pragma unroll
        for (int j = 0; j < TN; j += 4) {
            int col = bn0 + threadCol * TN + j;
            float4 v;
            v.x = acc[i][j + 0] + bias[col + 0];
            v.y = acc[i][j + 1] + bias[col + 1];
            v.z = acc[i][j + 2] + bias[col + 2];
            v.w = acc[i][j + 3] + bias[col + 3];
            *reinterpret_cast<float4*>(&C[(size_t)row * N + col]) = v;
        }
    }
}

// ---------------------------------------------------------------------------
// Shift source index. mode 1 = _shift1, mode 2 = _shift2. q = channel quarter.
// ---------------------------------------------------------------------------
__device__ __forceinline__ int shift_src(int mode, int q, int h, int w) {
    int hh = h, ww = w;
    if (mode == 1) {
        if      (q == 0) ww = max(w - 1, 0);
        else if (q == 1) ww = min(w + 1, Ww - 1);
        else if (q == 2) hh = max(h - 1, 0);
        else             hh = min(h + 1, Hh - 1);
    } else {
        if      (q == 0) hh = max(h - 1, 0);
        else if (q == 1) hh = min(h + 1, Hh - 1);
        else if (q == 2) ww = max(w - 1, 0);
        else             ww = min(w + 1, Ww - 1);
    }
    return hh * Ww + ww;
}

__global__ void zero_a_kernel() {
    int i = blockIdx.x * blockDim.x + threadIdx.x;
    if (i < Bn * NF) g_a[i] = 0.0f;
}

// a[b,c] = sum over hw of (x1 + x2 + x3). Grid (49, 16), 384 threads (c).
__global__ __launch_bounds__(384)
void reduce_a_kernel() {
    const int b = blockIdx.y;
    const int chunk = blockIdx.x;
    const int c = threadIdx.x;
    const int q = c / (NF / 4);
    const float* yb = g_y + (size_t)b * HW * D1;
    float acc = 0.0f;
    for (int j = 0; j < 64; j++) {
        int hw = chunk * 64 + j;
        int h = hw / Ww, w = hw % Ww;
        int s1 = shift_src(1, q, h, w);
        int s2 = shift_src(2, q, h, w);
        acc += yb[(size_t)s1 * D1 + c]
             + yb[(size_t)s2 * D1 + NF + c]
             + yb[(size_t)hw * D1 + 2 * NF + c];
    }
    atomicAdd(&g_a[b * NF + c], acc);
}

// Per-batch: h = gelu(a@Wg1); ahat = h@Wg2; abar = softmax_K(ahat). 16 blocks x 384.
__global__ __launch_bounds__(384)
void mlp_softmax_kernel(const float* __restrict__ Wg1,
                        const float* __restrict__ Wg2) {
    __shared__ float a_s[NF];
    __shared__ float h_s[NF];
    const int b = blockIdx.x;
    const int c = threadIdx.x;

    a_s[c] = g_a[b * NF + c];
    __syncthreads();

    float acc = 0.0f;
    for (int i = 0; i < NF; i++) acc += a_s[i] * Wg1[i * NF + c];
    // JAX gelu (approximate=True): tanh form
    float x = acc;
    float t = tanhf(0.7978845608028654f * (x + 0.044715f * x * x * x));
    h_s[c] = 0.5f * x * (1.0f + t);
    __syncthreads();

    float ah[KK];
    #pragma unroll
    for (int k = 0; k < KK; k++) {
        float s = 0.0f;
        for (int i = 0; i < NF; i++) s += h_s[i] * Wg2[i * D1 + k * NF + c];
        ah[k] = s;
    }
    float m = fmaxf(ah[0], fmaxf(ah[1], ah[2]));
    float e0 = expf(ah[0] - m), e1 = expf(ah[1] - m), e2 = expf(ah[2] - m);
    float inv = 1.0f / (e0 + e1 + e2);
    g_abar[b * D1 + 0 * NF + c] = e0 * inv;
    g_abar[b * D1 + 1 * NF + c] = e1 * inv;
    g_abar[b * D1 + 2 * NF + c] = e2 * inv;
}

// out[b,hw,c] = sum_k abar[b,k,c] * xs[b,k,hw,c]. Grid (49, 16), 384 threads.
__global__ __launch_bounds__(384)
void combine_kernel() {
    __shared__ float ab[D1];
    const int b = blockIdx.y;
    const int chunk = blockIdx.x;
    const int c = threadIdx.x;

    for (int i = c; i < D1; i += NF) ab[i] = g_abar[b * D1 + i];
    __syncthreads();

    const int q = c / (NF / 4);
    const float a0 = ab[c], a1 = ab[NF + c], a2 = ab[2 * NF + c];
    const float* yb = g_y + (size_t)b * HW * D1;
    float* ob = g_out + (size_t)b * HW * NF;

    for (int j = 0; j < 64; j++) {
        int hw = chunk * 64 + j;
        int h = hw / Ww, w = hw % Ww;
        int s1 = shift_src(1, q, h, w);
        int s2 = shift_src(2, q, h, w);
        ob[(size_t)hw * NF + c] =
            a0 * yb[(size_t)s1 * D1 + c] +
            a1 * yb[(size_t)s2 * D1 + NF + c] +
            a2 * yb[(size_t)hw * D1 + 2 * NF + c];
    }
}

// ---------------------------------------------------------------------------
extern "C" void kernel_launch(void* const* d_in, const int* in_sizes, int n_in,
                              void* d_out, int out_size) {
    const float* x   = (const float*)d_in[0];
    const float* W1  = (const float*)d_in[1];
    const float* b1  = (const float*)d_in[2];
    const float* Wg1 = (const float*)d_in[3];
    const float* Wg2 = (const float*)d_in[4];
    const float* W2  = (const float*)d_in[5];
    const float* b2  = (const float*)d_in[6];
    float* out = (float*)d_out;

    float *y_p = nullptr, *out_p = nullptr;
    cudaGetSymbolAddress((void**)&y_p, g_y);
    cudaGetSymbolAddress((void**)&out_p, g_out);

    // 1) y = x @ W1 + b1  (50176 x 384 x 1152)
    {
        dim3 grid(D1 / 128, NROW / 128);
        sgemm_bias<<<grid, 256>>>(x, W1, b1, y_p, NROW, D1, CIN);
    }
    // 2) a = sum over (k, hw) of shifted y
    zero_a_kernel<<<(Bn * NF + 255) / 256, 256>>>();
    reduce_a_kernel<<<dim3(HW / 64, Bn), NF>>>();
    // 3) abar = softmax_K( gelu(a@Wg1) @ Wg2 )
    mlp_softmax_kernel<<<Bn, NF>>>(Wg1, Wg2);
    // 4) out = sum_k abar * xs
    combine_kernel<<<dim3(HW / 64, Bn), NF>>>();
    // 5) final = out @ W2 + b2  (50176 x 384 x 384)
    {
        dim3 grid(NF / 128, NROW / 128);
        sgemm_bias<<<grid, 256>>>(out_p, W2, b2, out, NROW, NF, CIN);
    }
}

// round 3
// speedup vs baseline: 2.1400x; 2.1400x over previous
#include <cuda_runtime.h>
#include <cuda_bf16.h>
#include <cstdint>
#include <math.h>

// ---------------- problem constants ----------------
#define Bn   16
#define Hh   56
#define Ww   56
#define HW   (Hh*Ww)          // 3136
#define NROW (Bn*HW)          // 50176
#define CIN  384
#define NF   384
#define KK   3
#define D1   (NF*KK)          // 1152

// ---------------- device scratch ----------------
__device__ float          g_y[(size_t)NROW * D1];       // 231 MB fp32 y
__device__ __nv_bfloat16  g_xh[(size_t)NROW * CIN];
__device__ __nv_bfloat16  g_xl[(size_t)NROW * CIN];
__device__ __nv_bfloat16  g_oh[(size_t)NROW * NF];
__device__ __nv_bfloat16  g_ol[(size_t)NROW * NF];
__device__ __nv_bfloat16  g_w1h[(size_t)D1 * CIN];      // W1^T [N,K]
__device__ __nv_bfloat16  g_w1l[(size_t)D1 * CIN];
__device__ __nv_bfloat16  g_w2h[(size_t)NF * NF];       // W2^T [N,K]
__device__ __nv_bfloat16  g_w2l[(size_t)NF * NF];
__device__ float g_a[Bn * NF];
__device__ float g_hpre[Bn * NF];
__device__ float g_ahat[Bn * D1];
__device__ float g_abar[Bn * D1];

// ---------------- helpers ----------------
__device__ __forceinline__ uint32_t smem_u32(const void* p) {
    uint32_t a;
    asm("{ .reg .u64 t; cvta.to.shared.u64 t, %1; cvt.u32.u64 %0, t; }" : "=r"(a) : "l"(p));
    return a;
}
__device__ __forceinline__ void cp16(uint32_t s, const void* g) {
    asm volatile("cp.async.cg.shared.global [%0], [%1], 16;" :: "r"(s), "l"(g));
}
__device__ __forceinline__ void ldsm_x4(uint32_t& r0, uint32_t& r1, uint32_t& r2,
                                        uint32_t& r3, uint32_t addr) {
    asm volatile("ldmatrix.sync.aligned.m8n8.x4.shared.b16 {%0,%1,%2,%3}, [%4];"
                 : "=r"(r0), "=r"(r1), "=r"(r2), "=r"(r3) : "r"(addr));
}
__device__ __forceinline__ void mma_bf16(float* d, const uint32_t* a,
                                         uint32_t b0, uint32_t b1) {
    asm volatile("mma.sync.aligned.m16n8k16.row.col.f32.bf16.bf16.f32 "
        "{%0,%1,%2,%3}, {%4,%5,%6,%7}, {%8,%9}, {%0,%1,%2,%3};"
        : "+f"(d[0]), "+f"(d[1]), "+f"(d[2]), "+f"(d[3])
        : "r"(a[0]), "r"(a[1]), "r"(a[2]), "r"(a[3]), "r"(b0), "r"(b1));
}

// ---------------- bf16-split HMMA GEMM ----------------
// C[M,N] = (Ah+Al)[M,K] @ (Bh+Bl)[N,K]^T + bias; drop Al*Bl.
// CTA tile 128x128x32, 8 warps (2x4), warp tile 64x32.
#define BM 128
#define BN 128
#define BK 32
#define PITCH 80                   // bytes per smem row (32 bf16 + pad) -> conflict-free ldmatrix
#define T_BYTES (128 * PITCH)      // 10240 per tile array
#define OFF_AH 0
#define OFF_AL (T_BYTES)
#define OFF_BH (2 * T_BYTES)
#define OFF_BL (3 * T_BYTES)
#define STAGE_BYTES (4 * T_BYTES)  // 40960
#define GEMM_SMEM (2 * STAGE_BYTES)

__device__ __forceinline__ void load_stage(
    uint32_t stg, const __nv_bfloat16* Ah, const __nv_bfloat16* Al,
    const __nv_bfloat16* Bh, const __nv_bfloat16* Bl,
    int bm0, int bn0, int k0, int K, int tid)
{
    #pragma unroll
    for (int t = 0; t < 2; ++t) {               // 512 chunks per array, 256 threads
        int idx = tid + t * 256;
        int r = idx >> 2, c = idx & 3;
        uint32_t so = r * PITCH + c * 16;
        size_t ga = (size_t)(bm0 + r) * K + k0 + c * 8;
        cp16(stg + OFF_AH + so, Ah + ga);
        cp16(stg + OFF_AL + so, Al + ga);
        size_t gb = (size_t)(bn0 + r) * K + k0 + c * 8;
        cp16(stg + OFF_BH + so, Bh + gb);
        cp16(stg + OFF_BL + so, Bl + gb);
    }
}

__global__ __launch_bounds__(256)
void gemm_bf16split(const __nv_bfloat16* __restrict__ Ah,
                    const __nv_bfloat16* __restrict__ Al,
                    const __nv_bfloat16* __restrict__ Bh,
                    const __nv_bfloat16* __restrict__ Bl,
                    const float* __restrict__ bias,
                    float* __restrict__ C, int M, int N, int K)
{
    extern __shared__ char smem[];
    const uint32_t sbase = smem_u32(smem);
    const int tid = threadIdx.x, wid = tid >> 5, lane = tid & 31;
    const int warp_m = wid >> 2, warp_n = wid & 3;      // 2 x 4
    const int bn0 = blockIdx.x * BN, bm0 = blockIdx.y * BM;
    const int NC = K / BK;                               // 12

    float acc[4][4][4] = {};

    // ldmatrix base offsets (within a stage, per k-step add ks*32 bytes)
    const int a_r = (lane & 15);                 // row within 16-row tile
    const int a_kb = ((lane >> 4) << 3) * 2;     // 0 or 16 bytes
    const int b_r = ((lane >> 4) << 3) + (lane & 7);
    const int b_kb = (((lane >> 3) & 1) << 3) * 2;

    load_stage(sbase, Ah, Al, Bh, Bl, bm0, bn0, 0, K, tid);
    asm volatile("cp.async.commit_group;" ::: "memory");

    for (int c = 0; c < NC; ++c) {
        if (c + 1 < NC) {
            load_stage(sbase + ((c + 1) & 1) * STAGE_BYTES,
                       Ah, Al, Bh, Bl, bm0, bn0, (c + 1) * BK, K, tid);
            asm volatile("cp.async.commit_group;" ::: "memory");
            asm volatile("cp.async.wait_group 1;" ::: "memory");
        } else {
            asm volatile("cp.async.wait_group 0;" ::: "memory");
        }
        __syncthreads();

        const uint32_t stg = sbase + (c & 1) * STAGE_BYTES;
        #pragma unroll
        for (int ks = 0; ks < 2; ++ks) {
            const int koff = ks * 32;            // 16 bf16 = 32 bytes
            uint32_t ah[4][4], al[4][4], bh[2][4], bl[2][4];
            #pragma unroll
            for (int i = 0; i < 4; ++i) {
                uint32_t ra = (warp_m * 64 + i * 16 + a_r) * PITCH + koff + a_kb;
                ldsm_x4(ah[i][0], ah[i][1], ah[i][2], ah[i][3], stg + OFF_AH + ra);
                ldsm_x4(al[i][0], al[i][1], al[i][2], al[i][3], stg + OFF_AL + ra);
            }
            #pragma unroll
            for (int jp = 0; jp < 2; ++jp) {
                uint32_t rb = (warp_n * 32 + jp * 16 + b_r) * PITCH + koff + b_kb;
                ldsm_x4(bh[jp][0], bh[jp][1], bh[jp][2], bh[jp][3], stg + OFF_BH + rb);
                ldsm_x4(bl[jp][0], bl[jp][1], bl[jp][2], bl[jp][3], stg + OFF_BL + rb);
            }
            #pragma unroll
            for (int i = 0; i < 4; ++i)
                #pragma unroll
                for (int j = 0; j < 4; ++j) {
                    const int jp = j >> 1, jj = j & 1;
                    uint32_t B0h = bh[jp][jj * 2], B1h = bh[jp][jj * 2 + 1];
                    uint32_t B0l = bl[jp][jj * 2], B1l = bl[jp][jj * 2 + 1];
                    mma_bf16(acc[i][j], ah[i], B0h, B1h);
                    mma_bf16(acc[i][j], ah[i], B0l, B1l);
                    mma_bf16(acc[i][j], al[i], B0h, B1h);
                }
        }
        __syncthreads();
    }

    // epilogue
    #pragma unroll
    for (int i = 0; i < 4; ++i) {
        int row0 = bm0 + warp_m * 64 + i * 16 + (lane >> 2);
        #pragma unroll
        for (int j = 0; j < 4; ++j) {
            int col = bn0 + warp_n * 32 + j * 8 + (lane & 3) * 2;
            float b0 = bias[col], b1 = bias[col + 1];
            float2 v0 = {acc[i][j][0] + b0, acc[i][j][1] + b1};
            float2 v1 = {acc[i][j][2] + b0, acc[i][j][3] + b1};
            *reinterpret_cast<float2*>(C + (size_t)row0 * N + col) = v0;
            *reinterpret_cast<float2*>(C + (size_t)(row0 + 8) * N + col) = v1;
        }
    }
}

// ---------------- conversion kernels ----------------
__device__ __forceinline__ void split1(float v, __nv_bfloat16& h, __nv_bfloat16& l) {
    h = __float2bfloat16_rn(v);
    l = __float2bfloat16_rn(v - __bfloat162float(h));
}

__global__ __launch_bounds__(256)
void split_pair_kernel(const float* __restrict__ src,
                       __nv_bfloat16* __restrict__ h, __nv_bfloat16* __restrict__ l, int n4) {
    int i = blockIdx.x * blockDim.x + threadIdx.x;
    if (i >= n4) return;
    float4 v = reinterpret_cast<const float4*>(src)[i];
    __nv_bfloat16 h0, h1, h2, h3, l0, l1, l2, l3;
    split1(v.x, h0, l0); split1(v.y, h1, l1); split1(v.z, h2, l2); split1(v.w, h3, l3);
    __nv_bfloat162* hp = reinterpret_cast<__nv_bfloat162*>(h);
    __nv_bfloat162* lp = reinterpret_cast<__nv_bfloat162*>(l);
    hp[2 * i]     = __nv_bfloat162{h0, h1};
    hp[2 * i + 1] = __nv_bfloat162{h2, h3};
    lp[2 * i]     = __nv_bfloat162{l0, l1};
    lp[2 * i + 1] = __nv_bfloat162{l2, l3};
}

// W [K,N] row-major -> Oh/Ol [N,K] bf16 (transpose + split)
__global__ void wsplit_kernel(const float* __restrict__ W,
                              __nv_bfloat16* __restrict__ Oh, __nv_bfloat16* __restrict__ Ol,
                              int K, int N) {
    __shared__ float t[32][33];
    int n0 = blockIdx.x * 32, k0 = blockIdx.y * 32;
    int tx = threadIdx.x, ty = threadIdx.y;
    #pragma unroll
    for (int r = 0; r < 4; r++)
        t[ty + 8 * r][tx] = W[(size_t)(k0 + ty + 8 * r) * N + n0 + tx];
    __syncthreads();
    #pragma unroll
    for (int r = 0; r < 4; r++) {
        int n = n0 + ty + 8 * r, k = k0 + tx;
        float v = t[tx][ty + 8 * r];
        __nv_bfloat16 h, l; split1(v, h, l);
        Oh[(size_t)n * K + k] = h;
        Ol[(size_t)n * K + k] = l;
    }
}

// ---------------- shift / gating path ----------------
__device__ __forceinline__ int shift_src(int mode, int q, int h, int w) {
    int hh = h, ww = w;
    if (mode == 1) {
        if      (q == 0) ww = max(w - 1, 0);
        else if (q == 1) ww = min(w + 1, Ww - 1);
        else if (q == 2) hh = max(h - 1, 0);
        else             hh = min(h + 1, Hh - 1);
    } else {
        if      (q == 0) hh = max(h - 1, 0);
        else if (q == 1) hh = min(h + 1, Hh - 1);
        else if (q == 2) ww = max(w - 1, 0);
        else             ww = min(w + 1, Ww - 1);
    }
    return hh * Ww + ww;
}

__global__ void zero_small_kernel() {
    int i = blockIdx.x * blockDim.x + threadIdx.x;
    if (i < Bn * NF) g_a[i] = 0.0f;
    else if (i < 2 * Bn * NF) g_hpre[i - Bn * NF] = 0.0f;
    else if (i < 2 * Bn * NF + Bn * D1) g_ahat[i - 2 * Bn * NF] = 0.0f;
}

__global__ __launch_bounds__(384)
void reduce_a_kernel() {
    const int b = blockIdx.y, chunk = blockIdx.x, c = threadIdx.x;
    const int q = c / (NF / 4);
    const float* yb = g_y + (size_t)b * HW * D1;
    float acc = 0.0f;
    for (int j = 0; j < 64; j++) {
        int hw = chunk * 64 + j;
        int h = hw / Ww, w = hw % Ww;
        int s1 = shift_src(1, q, h, w);
        int s2 = shift_src(2, q, h, w);
        acc += yb[(size_t)s1 * D1 + c]
             + yb[(size_t)s2 * D1 + NF + c]
             + yb[(size_t)hw * D1 + 2 * NF + c];
    }
    atomicAdd(&g_a[b * NF + c], acc);
}

__device__ __forceinline__ float gelu_t(float x) {
    float t = tanhf(0.7978845608028654f * (x + 0.044715f * x * x * x));
    return 0.5f * x * (1.0f + t);
}

__global__ __launch_bounds__(384)
void mlp_h_kernel(const float* __restrict__ Wg1) {
    __shared__ float as[96];
    const int b = blockIdx.x, iq = blockIdx.y, c = threadIdx.x;
    if (c < 96) as[c] = g_a[b * NF + iq * 96 + c];
    __syncthreads();
    float s = 0.0f;
    #pragma unroll 8
    for (int j = 0; j < 96; j++)
        s += as[j] * Wg1[(size_t)(iq * 96 + j) * NF + c];
    atomicAdd(&g_hpre[b * NF + c], s);
}

__global__ __launch_bounds__(384)
void mlp_ahat_kernel(const float* __restrict__ Wg2) {
    __shared__ float hs[96];
    const int b = blockIdx.x, iq = blockIdx.y, c = threadIdx.x;
    if (c < 96) hs[c] = gelu_t(g_hpre[b * NF + iq * 96 + c]);
    __syncthreads();
    float s0 = 0.0f, s1 = 0.0f, s2 = 0.0f;
    #pragma unroll 4
    for (int j = 0; j < 96; j++) {
        int i = iq * 96 + j;
        float hv = hs[j];
        s0 += hv * Wg2[(size_t)i * D1 + c];
        s1 += hv * Wg2[(size_t)i * D1 + NF + c];
        s2 += hv * Wg2[(size_t)i * D1 + 2 * NF + c];
    }
    atomicAdd(&g_ahat[b * D1 + c], s0);
    atomicAdd(&g_ahat[b * D1 + NF + c], s1);
    atomicAdd(&g_ahat[b * D1 + 2 * NF + c], s2);
}

__global__ __launch_bounds__(384)
void softmax_kernel() {
    const int b = blockIdx.x, c = threadIdx.x;
    float a0 = g_ahat[b * D1 + c];
    float a1 = g_ahat[b * D1 + NF + c];
    float a2 = g_ahat[b * D1 + 2 * NF + c];
    float m = fmaxf(a0, fmaxf(a1, a2));
    float e0 = expf(a0 - m), e1 = expf(a1 - m), e2 = expf(a2 - m);
    float inv = 1.0f / (e0 + e1 + e2);
    g_abar[b * D1 + c] = e0 * inv;
    g_abar[b * D1 + NF + c] = e1 * inv;
    g_abar[b * D1 + 2 * NF + c] = e2 * inv;
}

__global__ __launch_bounds__(384)
void combine_kernel() {
    __shared__ float ab[D1];
    const int b = blockIdx.y, chunk = blockIdx.x, c = threadIdx.x;
    for (int i = c; i < D1; i += NF) ab[i] = g_abar[b * D1 + i];
    __syncthreads();

    const int q = c / (NF / 4);
    const float a0 = ab[c], a1 = ab[NF + c], a2 = ab[2 * NF + c];
    const float* yb = g_y + (size_t)b * HW * D1;
    __nv_bfloat16* oh = g_oh + (size_t)b * HW * NF;
    __nv_bfloat16* ol = g_ol + (size_t)b * HW * NF;

    for (int j = 0; j < 64; j++) {
        int hw = chunk * 64 + j;
        int h = hw / Ww, w = hw % Ww;
        int s1 = shift_src(1, q, h, w);
        int s2 = shift_src(2, q, h, w);
        float v = a0 * yb[(size_t)s1 * D1 + c]
                + a1 * yb[(size_t)s2 * D1 + NF + c]
                + a2 * yb[(size_t)hw * D1 + 2 * NF + c];
        __nv_bfloat16 hv, lv; split1(v, hv, lv);
        oh[(size_t)hw * NF + c] = hv;
        ol[(size_t)hw * NF + c] = lv;
    }
}

// ---------------- launch ----------------
extern "C" void kernel_launch(void* const* d_in, const int* in_sizes, int n_in,
                              void* d_out, int out_size) {
    const float* x   = (const float*)d_in[0];
    const float* W1  = (const float*)d_in[1];
    const float* b1  = (const float*)d_in[2];
    const float* Wg1 = (const float*)d_in[3];
    const float* Wg2 = (const float*)d_in[4];
    const float* W2  = (const float*)d_in[5];
    const float* b2  = (const float*)d_in[6];
    float* out = (float*)d_out;

    float *y_p;
    __nv_bfloat16 *xh, *xl, *oh, *ol, *w1h, *w1l, *w2h, *w2l;
    cudaGetSymbolAddress((void**)&y_p, g_y);
    cudaGetSymbolAddress((void**)&xh, g_xh);
    cudaGetSymbolAddress((void**)&xl, g_xl);
    cudaGetSymbolAddress((void**)&oh, g_oh);
    cudaGetSymbolAddress((void**)&ol, g_ol);
    cudaGetSymbolAddress((void**)&w1h, g_w1h);
    cudaGetSymbolAddress((void**)&w1l, g_w1l);
    cudaGetSymbolAddress((void**)&w2h, g_w2h);
    cudaGetSymbolAddress((void**)&w2l, g_w2l);

    cudaFuncSetAttribute(gemm_bf16split,
                         cudaFuncAttributeMaxDynamicSharedMemorySize, GEMM_SMEM);

    // conversions
    split_pair_kernel<<<(NROW * CIN / 4 + 255) / 256, 256>>>(x, xh, xl, NROW * CIN / 4);
    wsplit_kernel<<<dim3(D1 / 32, CIN / 32), dim3(32, 8)>>>(W1, w1h, w1l, CIN, D1);
    wsplit_kernel<<<dim3(NF / 32, NF / 32), dim3(32, 8)>>>(W2, w2h, w2l, NF, NF);

    // GEMM1: y = x @ W1 + b1
    gemm_bf16split<<<dim3(D1 / BN, NROW / BM), 256, GEMM_SMEM>>>(
        xh, xl, w1h, w1l, b1, y_p, NROW, D1, CIN);

    // gating path
    zero_small_kernel<<<(2 * Bn * NF + Bn * D1 + 255) / 256, 256>>>();
    reduce_a_kernel<<<dim3(HW / 64, Bn), NF>>>();
    mlp_h_kernel<<<dim3(Bn, 4), NF>>>(Wg1);
    mlp_ahat_kernel<<<dim3(Bn, 4), NF>>>(Wg2);
    softmax_kernel<<<Bn, NF>>>();
    combine_kernel<<<dim3(HW / 64, Bn), NF>>>();

    // GEMM2: out = combined @ W2 + b2
    gemm_bf16split<<<dim3(NF / BN, NROW / BM), 256, GEMM_SMEM>>>(
        oh, ol, w2h, w2l, b2, out, NROW, NF, NF);
}